// round 2
// baseline (speedup 1.0000x reference)
#include <cuda_runtime.h>
#include <cstdint>

// Problem constants
#define T_STEPS 32
#define BATCH   512
#define ACT     64
#define POP     64
#define OUT_DIM 4096   // ACT*POP

// Packed fp32x2 ops (Blackwell sm_103a; ptxas never auto-fuses these)
#define FMA2(d, a, b, c) \
    asm("fma.rn.f32x2 %0, %1, %2, %3;" : "=l"(d) : "l"(a), "l"(b), "l"(c))
#define ADD2(d, a, b) \
    asm("add.rn.f32x2 %0, %1, %2;" : "=l"(d) : "l"(a), "l"(b))
#define UNPACK2(lo, hi, p) \
    asm("mov.b64 {%0, %1}, %2;" : "=f"(lo), "=f"(hi) : "l"(p))

__global__ void __launch_bounds__(128, 2)
ilc_snn_kernel(const float* __restrict__ x_seq,   // [T, B, OUT_DIM]
               const float* __restrict__ conn_w,  // [ACT, POP(o), POP(d)]
               const float* __restrict__ conn_b,  // [OUT_DIM]
               float* __restrict__ out)           // [T, B, OUT_DIM]
{
    __shared__ __align__(16) float Wt[64 * 64];   // Wt[d][o]  (transposed)
    __shared__ __align__(16) float bias_s[64];

    const int tid   = threadIdx.x;
    const int a     = blockIdx.x & 63;        // group
    const int chunk = blockIdx.x >> 6;        // batch chunk
    const int b     = chunk * 128 + tid;      // batch index for this thread

    // ---- Load W[a] transposed into smem: Wt[d*64 + o] = w[a, o, d] ----
    {
        const float* gw = conn_w + a * 4096;
        #pragma unroll
        for (int i = tid; i < 4096; i += 128) {
            int o = i >> 6;
            int d = i & 63;
            Wt[d * 64 + o] = gw[i];
        }
        if (tid < 64) bias_s[tid] = conn_b[a * 64 + tid];
    }
    __syncthreads();

    // ---- Per-thread state: v[64] scalar, fb packed as 32 x f32x2 ----
    float v[64];
    unsigned long long fbp[32];
    #pragma unroll
    for (int o = 0; o < 64; ++o) v[o] = 0.0f;
    #pragma unroll
    for (int j = 0; j < 32; ++j) fbp[j] = 0ull;   // fb0 = 0 (no bias at t=0)

    const size_t base = (size_t)b * OUT_DIM + (size_t)a * 64;
    const size_t tstr = (size_t)BATCH * OUT_DIM;  // stride between timesteps

    // Prefetch x for t = 0
    float4 xr[16];
    {
        const float4* xp = (const float4*)(x_seq + base);
        #pragma unroll
        for (int j = 0; j < 16; ++j) xr[j] = xp[j];
    }

    for (int t = 0; t < T_STEPS; ++t) {
        // ---------- Phase 1: elementwise IF update + spike write ----------
        unsigned m0 = 0u, m1 = 0u;  // 64-bit spike mask
        float4* op = (float4*)(out + (size_t)t * tstr + base);

        #pragma unroll
        for (int j = 0; j < 16; ++j) {
            float4 x = xr[j];
            float f0, f1, f2, f3;
            UNPACK2(f0, f1, fbp[2 * j]);
            UNPACK2(f2, f3, fbp[2 * j + 1]);

            // v = v + (x_t + fb)   (reference order)
            float v0 = v[4 * j + 0] + (x.x + f0);
            float v1 = v[4 * j + 1] + (x.y + f1);
            float v2 = v[4 * j + 2] + (x.z + f2);
            float v3 = v[4 * j + 3] + (x.w + f3);

            bool s0 = (v0 >= 1.0f);
            bool s1 = (v1 >= 1.0f);
            bool s2 = (v2 >= 1.0f);
            bool s3 = (v3 >= 1.0f);

            float4 o4;
            o4.x = s0 ? 1.0f : 0.0f;
            o4.y = s1 ? 1.0f : 0.0f;
            o4.z = s2 ? 1.0f : 0.0f;
            o4.w = s3 ? 1.0f : 0.0f;
            op[j] = o4;

            // hard reset
            v[4 * j + 0] = s0 ? 0.0f : v0;
            v[4 * j + 1] = s1 ? 0.0f : v1;
            v[4 * j + 2] = s2 ? 0.0f : v2;
            v[4 * j + 3] = s3 ? 0.0f : v3;

            // pack spike bits (compile-time shifts under full unroll)
            if (j < 8) {
                m0 |= ((unsigned)s0) << (4 * j + 0);
                m0 |= ((unsigned)s1) << (4 * j + 1);
                m0 |= ((unsigned)s2) << (4 * j + 2);
                m0 |= ((unsigned)s3) << (4 * j + 3);
            } else {
                m1 |= ((unsigned)s0) << (4 * j - 32);
                m1 |= ((unsigned)s1) << (4 * j - 31);
                m1 |= ((unsigned)s2) << (4 * j - 30);
                m1 |= ((unsigned)s3) << (4 * j - 29);
            }
        }

        // ---------- Prefetch x for t+1 (hidden under the matmul) ----------
        if (t + 1 < T_STEPS) {
            const float4* xp = (const float4*)(x_seq + (size_t)(t + 1) * tstr + base);
            #pragma unroll
            for (int j = 0; j < 16; ++j) xr[j] = xp[j];
        }

        // ---------- Phase 2: fb_new[o] = sum_{d: spike} Wt[d][o]  (+bias) ----------
        #pragma unroll
        for (int j = 0; j < 32; ++j) fbp[j] = 0ull;

        #pragma unroll
        for (int d = 0; d < 64; ++d) {
            unsigned bit = (d < 32) ? ((m0 >> d) & 1u) : ((m1 >> (d - 32)) & 1u);
            // packed (1.0f,1.0f) or (0,0); product with W is exact -> matches ref mul+sum
            unsigned long long s2p = bit ? 0x3f8000003f800000ull : 0ull;
            const ulonglong2* wr = (const ulonglong2*)(Wt + (d << 6));
            #pragma unroll
            for (int j = 0; j < 16; ++j) {
                ulonglong2 w = wr[j];                 // LDS.128, warp-broadcast
                FMA2(fbp[2 * j],     w.x, s2p, fbp[2 * j]);
                FMA2(fbp[2 * j + 1], w.y, s2p, fbp[2 * j + 1]);
            }
        }

        // bias added after the reduction (reference order: einsum(...) + bias)
        const unsigned long long* bp = (const unsigned long long*)bias_s;
        #pragma unroll
        for (int j = 0; j < 32; ++j) {
            ADD2(fbp[j], fbp[j], bp[j]);
        }
    }
}

extern "C" void kernel_launch(void* const* d_in, const int* in_sizes, int n_in,
                              void* d_out, int out_size)
{
    const float* x_seq  = (const float*)d_in[0];
    const float* conn_w = (const float*)d_in[1];
    const float* conn_b = (const float*)d_in[2];
    float* out = (float*)d_out;

    // 64 groups x 4 batch-chunks of 128 -> one thread per (batch, group) system
    ilc_snn_kernel<<<256, 128>>>(x_seq, conn_w, conn_b, out);
}

// round 3
// speedup vs baseline: 1.0002x; 1.0002x over previous
#include <cuda_runtime.h>
#include <cstdint>

// Problem constants
#define T_STEPS 32
#define BATCH   512
#define ACT     64
#define POP     64
#define OUT_DIM 4096   // ACT*POP

// Packed fp32x2 ops (Blackwell sm_103a; ptxas never auto-fuses these)
#define FMA2(d, a, b, c) \
    asm("fma.rn.f32x2 %0, %1, %2, %3;" : "=l"(d) : "l"(a), "l"(b), "l"(c))
#define ADD2(d, a, b) \
    asm("add.rn.f32x2 %0, %1, %2;" : "=l"(d) : "l"(a), "l"(b))
#define UNPACK2(lo, hi, p) \
    asm("mov.b64 {%0, %1}, %2;" : "=f"(lo), "=f"(hi) : "l"(p))

__global__ void __launch_bounds__(128, 2)
ilc_snn_kernel(const float* __restrict__ x_seq,   // [T, B, OUT_DIM]
               const float* __restrict__ conn_w,  // [ACT, POP(o), POP(d)]
               const float* __restrict__ conn_b,  // [OUT_DIM]
               float* __restrict__ out)           // [T, B, OUT_DIM]
{
    __shared__ __align__(16) float Wt[64 * 64];   // Wt[d][o]  (transposed)
    __shared__ __align__(16) float bias_s[64];

    const int tid   = threadIdx.x;
    const int a     = blockIdx.x & 63;        // group
    const int chunk = blockIdx.x >> 6;        // batch chunk
    const int b     = chunk * 128 + tid;      // batch index for this thread

    // ---- Load W[a] transposed into smem: Wt[d*64 + o] = w[a, o, d] ----
    {
        const float* gw = conn_w + a * 4096;
        #pragma unroll
        for (int i = tid; i < 4096; i += 128) {
            int o = i >> 6;
            int d = i & 63;
            Wt[d * 64 + o] = gw[i];
        }
        if (tid < 64) bias_s[tid] = conn_b[a * 64 + tid];
    }
    __syncthreads();

    // ---- Per-thread state: v[64] scalar, fb packed as 32 x f32x2 ----
    float v[64];
    unsigned long long fbp[32];
    #pragma unroll
    for (int o = 0; o < 64; ++o) v[o] = 0.0f;
    #pragma unroll
    for (int j = 0; j < 32; ++j) fbp[j] = 0ull;   // fb0 = 0 (no bias at t=0)

    const size_t base = (size_t)b * OUT_DIM + (size_t)a * 64;
    const size_t tstr = (size_t)BATCH * OUT_DIM;  // stride between timesteps

    // Prefetch x for t = 0
    float4 xr[16];
    {
        const float4* xp = (const float4*)(x_seq + base);
        #pragma unroll
        for (int j = 0; j < 16; ++j) xr[j] = xp[j];
    }

    for (int t = 0; t < T_STEPS; ++t) {
        // ---------- Phase 1: elementwise IF update + spike write ----------
        unsigned m0 = 0u, m1 = 0u;  // 64-bit spike mask
        float4* op = (float4*)(out + (size_t)t * tstr + base);

        #pragma unroll
        for (int j = 0; j < 16; ++j) {
            float4 x = xr[j];
            float f0, f1, f2, f3;
            UNPACK2(f0, f1, fbp[2 * j]);
            UNPACK2(f2, f3, fbp[2 * j + 1]);

            // v = v + (x_t + fb)   (reference order)
            float v0 = v[4 * j + 0] + (x.x + f0);
            float v1 = v[4 * j + 1] + (x.y + f1);
            float v2 = v[4 * j + 2] + (x.z + f2);
            float v3 = v[4 * j + 3] + (x.w + f3);

            bool s0 = (v0 >= 1.0f);
            bool s1 = (v1 >= 1.0f);
            bool s2 = (v2 >= 1.0f);
            bool s3 = (v3 >= 1.0f);

            float4 o4;
            o4.x = s0 ? 1.0f : 0.0f;
            o4.y = s1 ? 1.0f : 0.0f;
            o4.z = s2 ? 1.0f : 0.0f;
            o4.w = s3 ? 1.0f : 0.0f;
            op[j] = o4;

            // hard reset
            v[4 * j + 0] = s0 ? 0.0f : v0;
            v[4 * j + 1] = s1 ? 0.0f : v1;
            v[4 * j + 2] = s2 ? 0.0f : v2;
            v[4 * j + 3] = s3 ? 0.0f : v3;

            // pack spike bits (compile-time shifts under full unroll)
            if (j < 8) {
                m0 |= ((unsigned)s0) << (4 * j + 0);
                m0 |= ((unsigned)s1) << (4 * j + 1);
                m0 |= ((unsigned)s2) << (4 * j + 2);
                m0 |= ((unsigned)s3) << (4 * j + 3);
            } else {
                m1 |= ((unsigned)s0) << (4 * j - 32);
                m1 |= ((unsigned)s1) << (4 * j - 31);
                m1 |= ((unsigned)s2) << (4 * j - 30);
                m1 |= ((unsigned)s3) << (4 * j - 29);
            }
        }

        // ---------- Prefetch x for t+1 (hidden under the matmul) ----------
        if (t + 1 < T_STEPS) {
            const float4* xp = (const float4*)(x_seq + (size_t)(t + 1) * tstr + base);
            #pragma unroll
            for (int j = 0; j < 16; ++j) xr[j] = xp[j];
        }

        // ---------- Phase 2: fb_new[o] = sum_{d: spike} Wt[d][o]  (+bias) ----------
        #pragma unroll
        for (int j = 0; j < 32; ++j) fbp[j] = 0ull;

        #pragma unroll
        for (int d = 0; d < 64; ++d) {
            unsigned bit = (d < 32) ? ((m0 >> d) & 1u) : ((m1 >> (d - 32)) & 1u);
            // packed (1.0f,1.0f) or (0,0); product with W is exact -> matches ref mul+sum
            unsigned long long s2p = bit ? 0x3f8000003f800000ull : 0ull;
            const ulonglong2* wr = (const ulonglong2*)(Wt + (d << 6));
            #pragma unroll
            for (int j = 0; j < 16; ++j) {
                ulonglong2 w = wr[j];                 // LDS.128, warp-broadcast
                FMA2(fbp[2 * j],     w.x, s2p, fbp[2 * j]);
                FMA2(fbp[2 * j + 1], w.y, s2p, fbp[2 * j + 1]);
            }
        }

        // bias added after the reduction (reference order: einsum(...) + bias)
        const unsigned long long* bp = (const unsigned long long*)bias_s;
        #pragma unroll
        for (int j = 0; j < 32; ++j) {
            ADD2(fbp[j], fbp[j], bp[j]);
        }
    }
}

extern "C" void kernel_launch(void* const* d_in, const int* in_sizes, int n_in,
                              void* d_out, int out_size)
{
    const float* x_seq  = (const float*)d_in[0];
    const float* conn_w = (const float*)d_in[1];
    const float* conn_b = (const float*)d_in[2];
    float* out = (float*)d_out;

    // 64 groups x 4 batch-chunks of 128 -> one thread per (batch, group) system
    ilc_snn_kernel<<<256, 128>>>(x_seq, conn_w, conn_b, out);
}